// round 7
// baseline (speedup 1.0000x reference)
#include <cuda_runtime.h>
#include <cuda_bf16.h>

// NMU forward: y[b,o] = prod_d ( M_hat[d,o]*x[b,d] + (1 - M_hat[d,o]) )
//            = prod_d ( M_hat[d,o]*(x[b,d]-1) + 1 )
// B=16384, D=256, O=32, fp32.
//
// R7: rows packed into f32x2 via transposed smem.
//  - block = 512 thr (16 warps), 32 rows/block; warp w owns d in [16w,16w+16),
//    lane = o. m duplicated into both f32x2 halves ONCE at load (32 regs).
//  - us_t[d][r] (stride 36 words, pad keeps LDS.128 16B-aligned AND staging
//    STS.32 conflict-free since lane = r spans all 32 banks).
//  - hot loop: per d one LDS.128 broadcast -> (u[4rp..4rp+3][d]) -> two f2_fma
//    DIRECTLY (no dup movs), 4 product chains.
//  - partials packed by row-pairs -> pw smem -> 16-way mul2 tree epilogue.

#define NMU_D   256
#define NMU_O   32
#define NMU_R   32        // rows per block
#define NMU_S   36        // padded words per d-row of us_t
#define NMU_NW  16        // warps
#define NMU_DPW 16        // d's per warp

#define NMU_ONE2 0x3f8000003f800000ULL

__device__ __forceinline__ unsigned long long f2_fma(unsigned long long a,
                                                     unsigned long long b,
                                                     unsigned long long c) {
    unsigned long long d;
    asm("fma.rn.f32x2 %0, %1, %2, %3;" : "=l"(d) : "l"(a), "l"(b), "l"(c));
    return d;
}
__device__ __forceinline__ unsigned long long f2_mul(unsigned long long a,
                                                     unsigned long long b) {
    unsigned long long d;
    asm("mul.rn.f32x2 %0, %1, %2;" : "=l"(d) : "l"(a), "l"(b));
    return d;
}
__device__ __forceinline__ unsigned long long dup2(float v) {
    unsigned long long d;
    unsigned u = __float_as_uint(v);
    asm("mov.b64 %0, {%1, %1};" : "=l"(d) : "r"(u));
    return d;
}

__global__ void __launch_bounds__(512, 2)
nmu_kernel(const float* __restrict__ x, const float* __restrict__ M,
           float* __restrict__ out) {
    extern __shared__ unsigned long long smem[];
    unsigned long long* pw = smem;                         // [16 w][16 rp2][32 o] = 64 KB
    float* us = (float*)(smem + NMU_NW * 16 * NMU_O);      // [256 d][36]        = 36 KB

    const int tid  = threadIdx.x;
    const int warp = tid >> 5;
    const int o    = tid & 31;
    const int b0   = blockIdx.x * NMU_R;
    const int d0   = warp * NMU_DPW;

    // --- weights: scalar m duplicated into both f32x2 halves (once) ---
    unsigned long long m2[16];
    #pragma unroll
    for (int k = 0; k < 16; k++) {
        float mv = __saturatef(__ldg(M + (size_t)(d0 + k) * NMU_O + o));
        m2[k] = dup2(mv);
    }

    // --- stage transposed u = x - 1: thread (r = tid&31, dg = tid>>5) ---
    {
        const int r  = tid & 31;
        const int dg = tid >> 5;                 // 0..15, 16 d's each
        const float4* __restrict__ xg =
            (const float4*)(x + (size_t)(b0 + r) * NMU_D + dg * 16);
        #pragma unroll
        for (int j = 0; j < 4; j++) {
            float4 v = __ldg(xg + j);
            const int d = dg * 16 + j * 4;
            us[(d + 0) * NMU_S + r] = v.x - 1.0f;   // lane=r -> all 32 banks
            us[(d + 1) * NMU_S + r] = v.y - 1.0f;
            us[(d + 2) * NMU_S + r] = v.z - 1.0f;
            us[(d + 3) * NMU_S + r] = v.w - 1.0f;
        }
    }
    __syncthreads();

    // --- hot loop: 8 row-quad iterations, 16 d each ---
    #pragma unroll 1
    for (int rp = 0; rp < 8; rp++) {
        const float* __restrict__ ub = us + d0 * NMU_S + 4 * rp;  // 16B-aligned

        unsigned long long a01, b01, a23, b23, t01, t23;
        {   // k = 0, 1 : chain init
            ulonglong2 v0 = *(const ulonglong2*)(ub + 0 * NMU_S);
            a01 = f2_fma(m2[0], v0.x, NMU_ONE2);
            a23 = f2_fma(m2[0], v0.y, NMU_ONE2);
            ulonglong2 v1 = *(const ulonglong2*)(ub + 1 * NMU_S);
            b01 = f2_fma(m2[1], v1.x, NMU_ONE2);
            b23 = f2_fma(m2[1], v1.y, NMU_ONE2);
        }
        #pragma unroll
        for (int k = 2; k < 16; k += 2) {
            ulonglong2 ve = *(const ulonglong2*)(ub + (k + 0) * NMU_S);
            t01 = f2_fma(m2[k], ve.x, NMU_ONE2);
            t23 = f2_fma(m2[k], ve.y, NMU_ONE2);
            a01 = f2_mul(a01, t01);
            a23 = f2_mul(a23, t23);
            ulonglong2 vo = *(const ulonglong2*)(ub + (k + 1) * NMU_S);
            t01 = f2_fma(m2[k + 1], vo.x, NMU_ONE2);
            t23 = f2_fma(m2[k + 1], vo.y, NMU_ONE2);
            b01 = f2_mul(b01, t01);
            b23 = f2_mul(b23, t23);
        }

        // packed partials: rows (4rp,4rp+1) and (4rp+2,4rp+3)
        pw[((size_t)warp * 16 + 2 * rp + 0) * NMU_O + o] = f2_mul(a01, b01);
        pw[((size_t)warp * 16 + 2 * rp + 1) * NMU_O + o] = f2_mul(a23, b23);
    }
    __syncthreads();

    // --- epilogue: cell (rp2 = warp, o); product over 16 d-chunk slabs ---
    {
        const int rp2 = warp;                    // 0..15
        const unsigned long long* __restrict__ pp =
            pw + (size_t)rp2 * NMU_O + o;
        const int S = 16 * NMU_O;                // 512 ull between warp slabs

        unsigned long long v[8];
        #pragma unroll
        for (int w = 0; w < 8; w++)
            v[w] = f2_mul(pp[(2 * w) * S], pp[(2 * w + 1) * S]);
        unsigned long long c0 = f2_mul(v[0], v[1]);
        unsigned long long c1 = f2_mul(v[2], v[3]);
        unsigned long long c2 = f2_mul(v[4], v[5]);
        unsigned long long c3 = f2_mul(v[6], v[7]);
        unsigned long long pr = f2_mul(f2_mul(c0, c1), f2_mul(c2, c3));

        float lo = __uint_as_float((unsigned)(pr & 0xffffffffULL));
        float hi = __uint_as_float((unsigned)(pr >> 32));
        out[(size_t)(b0 + 2 * rp2 + 0) * NMU_O + o] = lo;   // coalesced
        out[(size_t)(b0 + 2 * rp2 + 1) * NMU_O + o] = hi;
    }
}

extern "C" void kernel_launch(void* const* d_in, const int* in_sizes, int n_in,
                              void* d_out, int out_size) {
    const float* x = (const float*)d_in[0];   // [16384, 256]
    const float* M = (const float*)d_in[1];   // [256, 32]
    float* out = (float*)d_out;               // [16384, 32]

    const int B = in_sizes[0] / NMU_D;        // 16384

    const size_t smem_bytes = (size_t)NMU_NW * 16 * NMU_O * 8   // pw 64 KB
                            + (size_t)NMU_D * NMU_S * 4;        // us  36 KB
    cudaFuncSetAttribute(nmu_kernel,
                         cudaFuncAttributeMaxDynamicSharedMemorySize,
                         (int)smem_bytes);

    nmu_kernel<<<B / NMU_R, 512, smem_bytes>>>(x, M, out);
}

// round 8
// speedup vs baseline: 1.3178x; 1.3178x over previous
#include <cuda_runtime.h>
#include <cuda_bf16.h>

// NMU forward: y[b,o] = prod_d ( M_hat[d,o]*x[b,d] + (1 - M_hat[d,o]) )
//            = prod_d ( M_hat[d,o]*(x[b,d]-1) + 1 )
// B=16384, D=256, O=32, fp32.
//
// R8 = R5 skeleton (best so far) + 4 independent product chains (dep depth
// 32->12 cyc) + 16 rows/block (half the CTAs, amortized staging/epilogue).
//  - block = 256 thr (8 warps), warp owns 32 d's, lane = o.
//  - m2[16] packed (m[d],m[d+1]) f32x2 in registers, loaded once.
//  - u = x-1 staged d-major in smem via float4 copy (cheap, conflict-free).
//  - hot loop per row: 8 broadcast LDS.128 + 16 fma2 + 16 mul2, 4 chains.
//  - 8-wide partial combine through smem, 2 outputs/thread.

#define NMU_D   256
#define NMU_O   32
#define NMU_R   16        // rows per block
#define NMU_NW  8         // warps per block
#define NMU_DPW 32        // d's per warp

#define NMU_ONE2 0x3f8000003f800000ULL

__device__ __forceinline__ unsigned long long f2_fma(unsigned long long a,
                                                     unsigned long long b,
                                                     unsigned long long c) {
    unsigned long long d;
    asm("fma.rn.f32x2 %0, %1, %2, %3;" : "=l"(d) : "l"(a), "l"(b), "l"(c));
    return d;
}
__device__ __forceinline__ unsigned long long f2_mul(unsigned long long a,
                                                     unsigned long long b) {
    unsigned long long d;
    asm("mul.rn.f32x2 %0, %1, %2;" : "=l"(d) : "l"(a), "l"(b));
    return d;
}
__device__ __forceinline__ unsigned long long pack2(float a, float b) {
    unsigned long long d;
    asm("mov.b64 %0, {%1, %2};" : "=l"(d)
        : "r"(__float_as_uint(a)), "r"(__float_as_uint(b)));
    return d;
}

__global__ void __launch_bounds__(256, 4)
nmu_kernel(const float* __restrict__ x, const float* __restrict__ M,
           float* __restrict__ out) {
    __shared__ float us[NMU_R * NMU_D];            // 16 KB  (x - 1)
    __shared__ float pw[NMU_NW * NMU_R * NMU_O];   // 16 KB  partials

    const int tid  = threadIdx.x;
    const int warp = tid >> 5;
    const int o    = tid & 31;
    const int b0   = blockIdx.x * NMU_R;
    const int d0   = warp * NMU_DPW;

    // --- weights: 16 packed m-pairs in registers (coalesced, L1/L2-hot) ---
    unsigned long long m2[16];
    {
        const float* __restrict__ Mg = M + (size_t)d0 * NMU_O + o;
        #pragma unroll
        for (int k = 0; k < 16; k++) {
            float a = __saturatef(__ldg(Mg + (2 * k + 0) * NMU_O));
            float b = __saturatef(__ldg(Mg + (2 * k + 1) * NMU_O));
            m2[k] = pack2(a, b);
        }
    }

    // --- stage u = x - 1 (coalesced float4, subtract folded into copy) ---
    {
        const float4* __restrict__ xg = (const float4*)(x + (size_t)b0 * NMU_D);
        float4* us4 = (float4*)us;
        #pragma unroll
        for (int i = 0; i < (NMU_R * NMU_D / 4) / 256; i++) {   // 4 iters
            float4 v = xg[tid + i * 256];
            v.x -= 1.0f; v.y -= 1.0f; v.z -= 1.0f; v.w -= 1.0f;
            us4[tid + i * 256] = v;
        }
    }
    __syncthreads();

    // --- hot loop: 16 rows; 4 independent product chains per row ---
    #pragma unroll 2
    for (int r = 0; r < NMU_R; r++) {
        const ulonglong2* __restrict__ ur =
            (const ulonglong2*)(us + r * NMU_D + d0);

        unsigned long long c0, c1, c2, c3;
        {   // d0 .. d0+7 : chain inits
            ulonglong2 v0 = ur[0], v1 = ur[1];
            c0 = f2_fma(m2[0], v0.x, NMU_ONE2);
            c1 = f2_fma(m2[1], v0.y, NMU_ONE2);
            c2 = f2_fma(m2[2], v1.x, NMU_ONE2);
            c3 = f2_fma(m2[3], v1.y, NMU_ONE2);
        }
        {   // d0+8 .. d0+15
            ulonglong2 v2 = ur[2], v3 = ur[3];
            c0 = f2_mul(c0, f2_fma(m2[4], v2.x, NMU_ONE2));
            c1 = f2_mul(c1, f2_fma(m2[5], v2.y, NMU_ONE2));
            c2 = f2_mul(c2, f2_fma(m2[6], v3.x, NMU_ONE2));
            c3 = f2_mul(c3, f2_fma(m2[7], v3.y, NMU_ONE2));
        }
        {   // d0+16 .. d0+23
            ulonglong2 v4 = ur[4], v5 = ur[5];
            c0 = f2_mul(c0, f2_fma(m2[ 8], v4.x, NMU_ONE2));
            c1 = f2_mul(c1, f2_fma(m2[ 9], v4.y, NMU_ONE2));
            c2 = f2_mul(c2, f2_fma(m2[10], v5.x, NMU_ONE2));
            c3 = f2_mul(c3, f2_fma(m2[11], v5.y, NMU_ONE2));
        }
        {   // d0+24 .. d0+31
            ulonglong2 v6 = ur[6], v7 = ur[7];
            c0 = f2_mul(c0, f2_fma(m2[12], v6.x, NMU_ONE2));
            c1 = f2_mul(c1, f2_fma(m2[13], v6.y, NMU_ONE2));
            c2 = f2_mul(c2, f2_fma(m2[14], v7.x, NMU_ONE2));
            c3 = f2_mul(c3, f2_fma(m2[15], v7.y, NMU_ONE2));
        }

        unsigned long long pr = f2_mul(f2_mul(c0, c1), f2_mul(c2, c3));
        float lo = __uint_as_float((unsigned)(pr & 0xffffffffULL));
        float hi = __uint_as_float((unsigned)(pr >> 32));
        pw[(warp * NMU_R + r) * NMU_O + o] = lo * hi;   // conflict-free STS.32
    }
    __syncthreads();

    // --- combine 8 warp-partials; 2 outputs per thread ---
    #pragma unroll
    for (int i = 0; i < 2; i++) {
        const int idx = tid + i * 256;      // 0..511
        const int row = idx >> 5;           // 0..15
        const int oo  = idx & 31;
        const float* pp = pw + row * NMU_O + oo;
        const int S = NMU_R * NMU_O;        // 512 floats between warp slabs
        float a0 = pp[0 * S] * pp[1 * S];
        float a1 = pp[2 * S] * pp[3 * S];
        float a2 = pp[4 * S] * pp[5 * S];
        float a3 = pp[6 * S] * pp[7 * S];
        out[(size_t)(b0 + row) * NMU_O + oo] = (a0 * a1) * (a2 * a3);
    }
}

extern "C" void kernel_launch(void* const* d_in, const int* in_sizes, int n_in,
                              void* d_out, int out_size) {
    const float* x = (const float*)d_in[0];   // [16384, 256]
    const float* M = (const float*)d_in[1];   // [256, 32]
    float* out = (float*)d_out;               // [16384, 32]

    const int B = in_sizes[0] / NMU_D;        // 16384

    nmu_kernel<<<B / NMU_R, 256>>>(x, M, out);
}